// round 9
// baseline (speedup 1.0000x reference)
#include <cuda_runtime.h>
#include <math.h>

#define NPTS 1024
#define TLEN 64
#define CDIM 256
#define NTILE 16                         // 1024 / 64
#define NBLK (NTILE * (NTILE + 1) / 2)   // 136 triangular tiles
#define NPROD_WARPS (NBLK * 8)           // 1088 producer warps

typedef unsigned int uint32;

// Scratch (__device__ globals — zero-init at load; all reset-free except g_scnt).
__device__ uint32 g_xtf[2][NPTS * CDIM];   // tf32 means
__device__ float  g_normp[2][8][NPTS];     // per-slice norm partials
__device__ float  g_rs2[2][NTILE][NPTS];   // row-sum contributions, slot = other tile coord
__device__ double g_accb[NBLK][3];         // per-block scalar sums
__device__ unsigned int g_scnt[8];         // slice completion counters (init each call)
__device__ unsigned int g_ticket;          // monotonic ticket (modular, no reset)

#define BAR1() asm volatile("bar.sync 1, 256;" ::: "memory")

__device__ __forceinline__ uint32 f2tf(float v) {
    uint32 r;
    asm("cvt.rna.tf32.f32 %0, %1;" : "=r"(r) : "f"(v));
    return r;
}
__device__ __forceinline__ void mma_tf32(float* c,
                                         uint32 a0, uint32 a1, uint32 a2, uint32 a3,
                                         uint32 b0, uint32 b1) {
    asm("mma.sync.aligned.m16n8k8.row.col.f32.tf32.tf32.f32 "
        "{%0,%1,%2,%3},{%4,%5,%6,%7},{%8,%9},{%0,%1,%2,%3};"
        : "+f"(c[0]), "+f"(c[1]), "+f"(c[2]), "+f"(c[3])
        : "r"(a0), "r"(a1), "r"(a2), "r"(a3), "r"(b0), "r"(b1));
}

__device__ __forceinline__ void wait_slice(int s) {
    if ((threadIdx.x & 31) == 0) {
        volatile unsigned int* p = &g_scnt[s];
        while (*p < (unsigned)NPROD_WARPS) __nanosleep(256);
    }
    __syncwarp();
    __threadfence();
}

__global__ void init_kernel() {
    if (threadIdx.x < 8) g_scnt[threadIdx.x] = 0u;
}

// ---------------------------------------------------------------------------
// Fused kernel: 136 blocks x 512 threads, all co-resident.
//   threads 256..511 (8 warps): PRODUCERS — slice-major time-mean streaming.
//   threads 0..255   (8 warps): CONSUMERS — r7 tf32-mma triangular gemm,
//     chunk c gated on slice c; fused stats; modular-ticket finalize.
// ---------------------------------------------------------------------------
__global__ void __launch_bounds__(512, 1) fused_kernel(
    const float* __restrict__ ina, const float* __restrict__ inb,
    float* __restrict__ out) {
    const int tid = threadIdx.x;
    const int tb  = blockIdx.x;

    // ======================= PRODUCER HALF =======================
    if (tid >= 256) {
        const int pw   = (tid - 256) >> 5;   // producer warp 0..7
        const int lane = tid & 31;
        for (int s = 0; s < 8; ++s) {
            for (int u = tb * 8 + pw; u < 2048; u += NPROD_WARPS) {
                const int n = u >> 1, w = u & 1;
                const float* __restrict__ src = (w == 0) ? ina : inb;
                const float* base = src + (size_t)n * (TLEN * CDIM) + s * 32 + lane;
                float c0 = 0.f, c1 = 0.f, c2 = 0.f, c3 = 0.f;
#pragma unroll
                for (int t = 0; t < 16; ++t) {
                    c0 += __ldcs(base + (size_t)(4 * t + 0) * CDIM);
                    c1 += __ldcs(base + (size_t)(4 * t + 1) * CDIM);
                    c2 += __ldcs(base + (size_t)(4 * t + 2) * CDIM);
                    c3 += __ldcs(base + (size_t)(4 * t + 3) * CDIM);
                }
                const float m = ((c0 + c1) + (c2 + c3)) * (1.0f / TLEN);
                g_xtf[w][(size_t)n * CDIM + s * 32 + lane] = f2tf(m);
                float sq = m * m;
#pragma unroll
                for (int off = 16; off > 0; off >>= 1)
                    sq += __shfl_down_sync(0xffffffffu, sq, off);
                if (lane == 0) g_normp[w][s][n] = sq;
            }
            __threadfence();
            if (lane == 0) atomicAdd(&g_scnt[s], 1u);
        }
        return;
    }

    // ======================= CONSUMER HALF =======================
    int by = (int)((__fsqrt_rn(8.f * (float)tb + 1.f) - 1.f) * 0.5f);
    while ((by + 1) * (by + 2) / 2 <= tb) ++by;
    while (by * (by + 1) / 2 > tb) --by;
    const int bx = tb - by * (by + 1) / 2;
    const bool diag = (bx == by);
    const int I = bx * 64;   // rows
    const int J = by * 64;   // cols

    __shared__ uint32 sA[2][64][36];   // [w][m][k] tf32 bits (I-rows)
    __shared__ uint32 sB[2][64][36];   // [w][n][k] tf32 bits (J-rows)
    __shared__ float sh_rs[2][64], sh_cs[2][64];
    __shared__ float snorm[2][128];
    __shared__ float sh_p[3][8];
    __shared__ unsigned int s_last;

    const int warp = tid >> 5, lane = tid & 31;
    const int wr = warp >> 1, wc = warp & 1;   // 4x2 warp grid
    const int g = lane >> 2, tig = lane & 3;

    if (tid < 128) {
        const int w2 = tid >> 6;
        sh_rs[w2][tid & 63] = 0.f;
        sh_cs[w2][tid & 63] = 0.f;
    }

    float cx[4][4], cy[4][4];
#pragma unroll
    for (int t = 0; t < 4; ++t)
#pragma unroll
        for (int q = 0; q < 4; ++q) { cx[t][q] = 0.f; cy[t][q] = 0.f; }

    // fill mapping: m = tid>>2 (0..63), kq = (tid&3)*8 : 8 uint32 (2 uint4)
    const int m  = tid >> 2;
    const int kq = (tid & 3) * 8;

    uint4 fA[2][2], fB[2][2];
    wait_slice(0);
#pragma unroll
    for (int w = 0; w < 2; ++w)
#pragma unroll
        for (int q = 0; q < 2; ++q) {
            fA[w][q] = *(const uint4*)(g_xtf[w] + (size_t)(I + m) * CDIM + kq + 4 * q);
            fB[w][q] = *(const uint4*)(g_xtf[w] + (size_t)(J + m) * CDIM + kq + 4 * q);
        }

    for (int c = 0; c < 8; ++c) {
        BAR1();
#pragma unroll
        for (int w = 0; w < 2; ++w)
#pragma unroll
            for (int q = 0; q < 2; ++q) {
                *(uint4*)&sA[w][m][kq + 4 * q] = fA[w][q];
                *(uint4*)&sB[w][m][kq + 4 * q] = fB[w][q];
            }
        BAR1();
        if (c < 7) {
            wait_slice(c + 1);
            const int k0 = (c + 1) * 32;
#pragma unroll
            for (int w = 0; w < 2; ++w)
#pragma unroll
                for (int q = 0; q < 2; ++q) {
                    fA[w][q] = *(const uint4*)(g_xtf[w] + (size_t)(I + m) * CDIM + k0 + kq + 4 * q);
                    fB[w][q] = *(const uint4*)(g_xtf[w] + (size_t)(J + m) * CDIM + k0 + kq + 4 * q);
                }
        }
#pragma unroll
        for (int kk = 0; kk < 4; ++kk) {
            const int kb = kk * 8;
            const int r0 = 16 * wr + g, r1 = r0 + 8;
            const uint32 ax0 = sA[0][r0][kb + tig];
            const uint32 ax1 = sA[0][r1][kb + tig];
            const uint32 ax2 = sA[0][r0][kb + tig + 4];
            const uint32 ax3 = sA[0][r1][kb + tig + 4];
            const uint32 ay0 = sA[1][r0][kb + tig];
            const uint32 ay1 = sA[1][r1][kb + tig];
            const uint32 ay2 = sA[1][r0][kb + tig + 4];
            const uint32 ay3 = sA[1][r1][kb + tig + 4];
#pragma unroll
            for (int t = 0; t < 4; ++t) {
                const int nr = 32 * wc + 8 * t + g;
                const uint32 bx0 = sB[0][nr][kb + tig];
                const uint32 bx1 = sB[0][nr][kb + tig + 4];
                mma_tf32(cx[t], ax0, ax1, ax2, ax3, bx0, bx1);
                const uint32 by0 = sB[1][nr][kb + tig];
                const uint32 by1 = sB[1][nr][kb + tig + 4];
                mma_tf32(cy[t], ay0, ay1, ay2, ay3, by0, by1);
            }
        }
    }

    // norms table (all slices complete after chunk-7 gate)
    BAR1();
    {
        const int w2 = tid & 1, r = tid >> 1;          // r = 0..127
        const int n = (r < 64) ? (I + r) : (J + r - 64);
        float s = 0.f;
#pragma unroll
        for (int q = 0; q < 8; ++q) s += g_normp[w2][q][n];
        snorm[w2][r] = s;
    }
    BAR1();

    // -------- Epilogue: distances from gram, fused statistics --------
    const int lr0 = 16 * wr + g, lr1 = lr0 + 8;        // local rows
    const float nIx0 = snorm[0][lr0], nIx1 = snorm[0][lr1];
    const float nIy0 = snorm[1][lr0], nIy1 = snorm[1][lr1];
    const int gr0 = I + lr0, gr1 = I + lr1;

    float pxy = 0.f, pxx = 0.f, pyy = 0.f;
    float prx0 = 0.f, prx1 = 0.f, pry0 = 0.f, pry1 = 0.f;

#pragma unroll
    for (int t = 0; t < 4; ++t) {
        const int colL = 32 * wc + 8 * t + 2 * tig;    // local col
        const int gcA = J + colL, gcB = gcA + 1;
        const float nJxA = snorm[0][64 + colL], nJxB = snorm[0][64 + colL + 1];
        const float nJyA = snorm[1][64 + colL], nJyB = snorm[1][64 + colL + 1];

        float dx00 = sqrtf(fmaxf(nIx0 + nJxA - 2.f * cx[t][0], 0.f) + 1e-12f);
        float dx01 = sqrtf(fmaxf(nIx0 + nJxB - 2.f * cx[t][1], 0.f) + 1e-12f);
        float dx10 = sqrtf(fmaxf(nIx1 + nJxA - 2.f * cx[t][2], 0.f) + 1e-12f);
        float dx11 = sqrtf(fmaxf(nIx1 + nJxB - 2.f * cx[t][3], 0.f) + 1e-12f);
        float dy00 = sqrtf(fmaxf(nIy0 + nJyA - 2.f * cy[t][0], 0.f) + 1e-12f);
        float dy01 = sqrtf(fmaxf(nIy0 + nJyB - 2.f * cy[t][1], 0.f) + 1e-12f);
        float dy10 = sqrtf(fmaxf(nIy1 + nJyA - 2.f * cy[t][2], 0.f) + 1e-12f);
        float dy11 = sqrtf(fmaxf(nIy1 + nJyB - 2.f * cy[t][3], 0.f) + 1e-12f);

        if (gr0 == gcA) { dx00 = 1e-6f; dy00 = 1e-6f; }   // exact diagonal
        if (gr0 == gcB) { dx01 = 1e-6f; dy01 = 1e-6f; }
        if (gr1 == gcA) { dx10 = 1e-6f; dy10 = 1e-6f; }
        if (gr1 == gcB) { dx11 = 1e-6f; dy11 = 1e-6f; }

        pxy += dx00 * dy00 + dx01 * dy01 + dx10 * dy10 + dx11 * dy11;
        pxx += dx00 * dx00 + dx01 * dx01 + dx10 * dx10 + dx11 * dx11;
        pyy += dy00 * dy00 + dy01 * dy01 + dy10 * dy10 + dy11 * dy11;

        prx0 += dx00 + dx01; prx1 += dx10 + dx11;
        pry0 += dy00 + dy01; pry1 += dy10 + dy11;

        float vxA = dx00 + dx10, vxB = dx01 + dx11;
        float vyA = dy00 + dy10, vyB = dy01 + dy11;
#pragma unroll
        for (int s = 16; s >= 4; s >>= 1) {
            vxA += __shfl_down_sync(0xffffffffu, vxA, s);
            vxB += __shfl_down_sync(0xffffffffu, vxB, s);
            vyA += __shfl_down_sync(0xffffffffu, vyA, s);
            vyB += __shfl_down_sync(0xffffffffu, vyB, s);
        }
        if (g == 0) {
            atomicAdd(&sh_cs[0][colL],     vxA);
            atomicAdd(&sh_cs[0][colL + 1], vxB);
            atomicAdd(&sh_cs[1][colL],     vyA);
            atomicAdd(&sh_cs[1][colL + 1], vyB);
        }
    }

    prx0 += __shfl_down_sync(0xffffffffu, prx0, 2, 4);
    prx0 += __shfl_down_sync(0xffffffffu, prx0, 1, 4);
    prx1 += __shfl_down_sync(0xffffffffu, prx1, 2, 4);
    prx1 += __shfl_down_sync(0xffffffffu, prx1, 1, 4);
    pry0 += __shfl_down_sync(0xffffffffu, pry0, 2, 4);
    pry0 += __shfl_down_sync(0xffffffffu, pry0, 1, 4);
    pry1 += __shfl_down_sync(0xffffffffu, pry1, 2, 4);
    pry1 += __shfl_down_sync(0xffffffffu, pry1, 1, 4);
    if (tig == 0) {
        atomicAdd(&sh_rs[0][lr0], prx0);
        atomicAdd(&sh_rs[0][lr1], prx1);
        atomicAdd(&sh_rs[1][lr0], pry0);
        atomicAdd(&sh_rs[1][lr1], pry1);
    }

#pragma unroll
    for (int off = 16; off > 0; off >>= 1) {
        pxy += __shfl_down_sync(0xffffffffu, pxy, off);
        pxx += __shfl_down_sync(0xffffffffu, pxx, off);
        pyy += __shfl_down_sync(0xffffffffu, pyy, off);
    }
    if (lane == 0) { sh_p[0][warp] = pxy; sh_p[1][warp] = pxx; sh_p[2][warp] = pyy; }
    BAR1();

    // reset-free global stores (slot = other tile coordinate)
    if (tid < 64) {
        g_rs2[0][by][I + tid] = sh_rs[0][tid];
        g_rs2[1][by][I + tid] = sh_rs[1][tid];
        if (!diag) {
            g_rs2[0][bx][J + tid] = sh_cs[0][tid];
            g_rs2[1][bx][J + tid] = sh_cs[1][tid];
        }
    }
    if (tid == 0) {
        const double scl = diag ? 1.0 : 2.0;
        double s0 = 0, s1 = 0, s2 = 0;
#pragma unroll
        for (int q = 0; q < 8; ++q) { s0 += sh_p[0][q]; s1 += sh_p[1][q]; s2 += sh_p[2][q]; }
        g_accb[tb][0] = scl * s0;
        g_accb[tb][1] = scl * s1;
        g_accb[tb][2] = scl * s2;
    }

    // -------- last-block finalize (modular ticket, no reset needed) --------
    __threadfence();
    BAR1();
    if (tid == 0) s_last = ((atomicAdd(&g_ticket, 1u) % NBLK) == NBLK - 1) ? 1u : 0u;
    BAR1();
    if (s_last == 0u) return;
    __threadfence();

    double sRR = 0.0, sXX = 0.0, sYY = 0.0, sX = 0.0, sY = 0.0;
#pragma unroll
    for (int q = 0; q < 4; ++q) {
        const int n = tid + q * 256;
        double rx = 0.0, ry = 0.0;
#pragma unroll
        for (int h = 0; h < NTILE; ++h) {
            rx += (double)g_rs2[0][h][n];
            ry += (double)g_rs2[1][h][n];
        }
        sRR += rx * ry; sXX += rx * rx; sYY += ry * ry; sX += rx; sY += ry;
    }
    double aXY = 0.0, aXX2 = 0.0, aYY2 = 0.0;
    if (tid < NBLK) { aXY = g_accb[tid][0]; aXX2 = g_accb[tid][1]; aYY2 = g_accb[tid][2]; }

#pragma unroll
    for (int off = 16; off > 0; off >>= 1) {
        sRR += __shfl_down_sync(0xffffffffu, sRR, off);
        sXX += __shfl_down_sync(0xffffffffu, sXX, off);
        sYY += __shfl_down_sync(0xffffffffu, sYY, off);
        sX  += __shfl_down_sync(0xffffffffu, sX, off);
        sY  += __shfl_down_sync(0xffffffffu, sY, off);
        aXY += __shfl_down_sync(0xffffffffu, aXY, off);
        aXX2 += __shfl_down_sync(0xffffffffu, aXX2, off);
        aYY2 += __shfl_down_sync(0xffffffffu, aYY2, off);
    }
    __shared__ double sd[8][8];
    if (lane == 0) {
        sd[0][warp] = sRR; sd[1][warp] = sXX; sd[2][warp] = sYY;
        sd[3][warp] = sX;  sd[4][warp] = sY;
        sd[5][warp] = aXY; sd[6][warp] = aXX2; sd[7][warp] = aYY2;
    }
    BAR1();
    if (tid == 0) {
        double v[8];
#pragma unroll
        for (int j = 0; j < 8; ++j) {
            v[j] = 0.0;
#pragma unroll
            for (int q = 0; q < 8; ++q) v[j] += sd[j][q];
        }
        const double N = (double)NPTS, N2 = N * N;
        const double sumab = v[5] - (2.0 / N) * v[0] + (v[3] * v[4]) / N2;
        const double sumaa = v[6] - (2.0 / N) * v[1] + (v[3] * v[3]) / N2;
        const double sumbb = v[7] - (2.0 / N) * v[2] + (v[4] * v[4]) / N2;
        const double mxy = sumab / N2, mxx = sumaa / N2, myy = sumbb / N2;
        const double r = mxy / sqrt(mxx * myy + 1e-9);
        out[0] = (float)(1.0 - r);
    }
}

extern "C" void kernel_launch(void* const* d_in, const int* in_sizes, int n_in,
                              void* d_out, int out_size) {
    const float* a = (const float*)d_in[0];  // output_1 (1024,64,256) f32
    const float* b = (const float*)d_in[1];  // feature  (1024,64,256) f32
    // d_in[2] = mask, unused by the reference module.

    init_kernel<<<1, 32>>>();
    fused_kernel<<<NBLK, 512>>>(a, b, (float*)d_out);
}

// round 10
// speedup vs baseline: 1.6399x; 1.6399x over previous
#include <cuda_runtime.h>
#include <math.h>

#define NPTS 1024
#define TLEN 64
#define CDIM 256
#define NTILE 16                         // 1024 / 64
#define NBLK (NTILE * (NTILE + 1) / 2)   // 136 triangular tiles

typedef unsigned int uint32;

// Scratch (__device__ globals — no allocation allowed).
__device__ uint32 g_xtf[2][NPTS * CDIM]; // time-means pre-converted to tf32 bits
__device__ float  g_norm[2][NPTS];       // row squared norms (fp32 exact)
__device__ float  g_rs[2][NPTS];         // row sums of d (atomic-accumulated)
__device__ double g_acc[3];              // sum(dx*dy), sum(dx*dx), sum(dy*dy)
__device__ unsigned int g_ticket;        // last-block-done counter

__device__ __forceinline__ uint32 f2tf(float v) {
    uint32 r;
    asm("cvt.rna.tf32.f32 %0, %1;" : "=r"(r) : "f"(v));
    return r;
}
__device__ __forceinline__ void mma_tf32(float* c,
                                         uint32 a0, uint32 a1, uint32 a2, uint32 a3,
                                         uint32 b0, uint32 b1) {
    asm("mma.sync.aligned.m16n8k8.row.col.f32.tf32.tf32.f32 "
        "{%0,%1,%2,%3},{%4,%5,%6,%7},{%8,%9},{%0,%1,%2,%3};"
        : "+f"(c[0]), "+f"(c[1]), "+f"(c[2]), "+f"(c[3])
        : "r"(a0), "r"(a1), "r"(a2), "r"(a3), "r"(b0), "r"(b1));
}

// ---------------------------------------------------------------------------
// Kernel 1: time-mean over T + per-row squared norm + tf32 pre-conversion.
// (r7 proven: HBM-ceiling bound, ~24.5us) grid (512, 2), block 256.
// ---------------------------------------------------------------------------
__global__ void mean_norm_kernel(const float* __restrict__ a,
                                 const float* __restrict__ b) {
    const int w = blockIdx.y;
    const float* __restrict__ src = (w == 0) ? a : b;
    const int tid  = threadIdx.x;
    const int row  = tid >> 7;
    const int half = (tid >> 6) & 1;
    const int c4   = tid & 63;
    const int n    = blockIdx.x * 2 + row;

    if (blockIdx.x == 0) {   // fold init
#pragma unroll
        for (int r = 0; r < 4; ++r) g_rs[w][tid + 256 * r] = 0.f;
        if (w == 0 && tid == 0) {
            g_acc[0] = 0.0; g_acc[1] = 0.0; g_acc[2] = 0.0;
            g_ticket = 0u;
        }
    }

    const float4* __restrict__ p =
        (const float4*)(src + (size_t)n * (TLEN * CDIM)) + half * 32 * (CDIM / 4) + c4;
    float4 s0 = make_float4(0.f, 0.f, 0.f, 0.f);
    float4 s1 = make_float4(0.f, 0.f, 0.f, 0.f);
#pragma unroll
    for (int t = 0; t < 16; ++t) {
        float4 v0 = __ldcs(p + (size_t)(2 * t) * (CDIM / 4));
        float4 v1 = __ldcs(p + (size_t)(2 * t + 1) * (CDIM / 4));
        s0.x += v0.x; s0.y += v0.y; s0.z += v0.z; s0.w += v0.w;
        s1.x += v1.x; s1.y += v1.y; s1.z += v1.z; s1.w += v1.w;
    }
    float4 s;
    s.x = s0.x + s1.x; s.y = s0.y + s1.y; s.z = s0.z + s1.z; s.w = s0.w + s1.w;

    __shared__ float4 sh[2][2][64];
    __shared__ float part[2][2];
    sh[row][half][c4] = s;
    __syncthreads();

    if (half == 0) {
        const float4 o = sh[row][1][c4];
        const float inv = 1.0f / TLEN;
        float4 m;
        m.x = (s.x + o.x) * inv; m.y = (s.y + o.y) * inv;
        m.z = (s.z + o.z) * inv; m.w = (s.w + o.w) * inv;

        uint4 u;
        u.x = f2tf(m.x); u.y = f2tf(m.y); u.z = f2tf(m.z); u.w = f2tf(m.w);
        ((uint4*)(g_xtf[w] + (size_t)n * CDIM))[c4] = u;

        float sq = m.x * m.x + m.y * m.y + m.z * m.z + m.w * m.w;
#pragma unroll
        for (int off = 16; off > 0; off >>= 1)
            sq += __shfl_down_sync(0xffffffffu, sq, off);
        if ((c4 & 31) == 0) part[row][c4 >> 5] = sq;
    }
    __syncthreads();
    if ((tid & 127) == 0) g_norm[w][n] = part[row][0] + part[row][1];
}

// ---------------------------------------------------------------------------
// Kernel 2: triangular tf32-mma pairwise-distance GEMM, 512 threads:
//   warp-group 0 (warps 0-7):  x-matrix gram (r7 fragment code, half chain)
//   warp-group 1 (warps 8-15): y-matrix gram
// 16 warps/SM hides latency (r7 was 8 warps, issue 22%). y-distances staged
// through smem (overlaid on dead sA) for the cross-product pxy. Fused stats
// + ticket finalize. grid 136 = one wave.
// ---------------------------------------------------------------------------
__global__ void __launch_bounds__(512) gemm_mma_kernel(float* __restrict__ out) {
    const int tb = blockIdx.x;
    int by = (int)((__fsqrt_rn(8.f * (float)tb + 1.f) - 1.f) * 0.5f);
    while ((by + 1) * (by + 2) / 2 <= tb) ++by;
    while (by * (by + 1) / 2 > tb) --by;
    const int bx = tb - by * (by + 1) / 2;
    const bool diag = (bx == by);
    const int I = bx * 64;   // rows
    const int J = by * 64;   // cols

    __shared__ uint32 sA[2][64][36];   // [wg][m][k] tf32 bits (I-rows)
    __shared__ uint32 sB[2][64][36];   // [wg][n][k] tf32 bits (J-rows)
    __shared__ float sh_rs[2][64], sh_cs[2][64];
    __shared__ float sh_p[3][8];
    __shared__ unsigned int s_last;

    const int tid  = threadIdx.x;          // 0..511
    const int wg   = tid >> 8;             // 0: x, 1: y
    const int tid8 = tid & 255;
    const int warp8 = tid8 >> 5, lane = tid & 31;
    const int wr = warp8 >> 1, wc = warp8 & 1;   // 4x2 warp grid within group
    const int g = lane >> 2, tig = lane & 3;

    if (tid < 128) {
        const int w2 = tid >> 6;
        sh_rs[w2][tid & 63] = 0.f;
        sh_cs[w2][tid & 63] = 0.f;
    }

    float cc[4][4];
#pragma unroll
    for (int t = 0; t < 4; ++t)
#pragma unroll
        for (int q = 0; q < 4; ++q) cc[t][q] = 0.f;

    // fill mapping (per group): m = tid8>>2 (0..63), kq = (tid8&3)*8
    const int m  = tid8 >> 2;
    const int kq = (tid8 & 3) * 8;

    const uint32* __restrict__ XA = g_xtf[wg] + (size_t)(I + m) * CDIM + kq;
    const uint32* __restrict__ XB = g_xtf[wg] + (size_t)(J + m) * CDIM + kq;

    uint4 fA[2], fB[2];
    fA[0] = *(const uint4*)(XA);     fA[1] = *(const uint4*)(XA + 4);
    fB[0] = *(const uint4*)(XB);     fB[1] = *(const uint4*)(XB + 4);

    for (int c = 0; c < 8; ++c) {
        __syncthreads();
        *(uint4*)&sA[wg][m][kq]     = fA[0];
        *(uint4*)&sA[wg][m][kq + 4] = fA[1];
        *(uint4*)&sB[wg][m][kq]     = fB[0];
        *(uint4*)&sB[wg][m][kq + 4] = fB[1];
        __syncthreads();
        if (c < 7) {
            const int k0 = (c + 1) * 32;
            fA[0] = *(const uint4*)(XA + k0);  fA[1] = *(const uint4*)(XA + k0 + 4);
            fB[0] = *(const uint4*)(XB + k0);  fB[1] = *(const uint4*)(XB + k0 + 4);
        }
#pragma unroll
        for (int kk = 0; kk < 4; ++kk) {
            const int kb = kk * 8;
            const int r0 = 16 * wr + g, r1 = r0 + 8;
            const uint32 a0 = sA[wg][r0][kb + tig];
            const uint32 a1 = sA[wg][r1][kb + tig];
            const uint32 a2 = sA[wg][r0][kb + tig + 4];
            const uint32 a3 = sA[wg][r1][kb + tig + 4];
#pragma unroll
            for (int t = 0; t < 4; ++t) {
                const int nr = 32 * wc + 8 * t + g;
                const uint32 b0 = sB[wg][nr][kb + tig];
                const uint32 b1 = sB[wg][nr][kb + tig + 4];
                mma_tf32(cc[t], a0, a1, a2, a3, b0, b1);
            }
        }
    }

    __syncthreads();   // mainloop done; sA becomes dead -> reuse as gy
    float* gy = (float*)&sA[0][0][0];   // 64 x 65 padded tile (4160 <= 4608 words)

    // -------- distances for own matrix (diag override) --------
    const int lr0 = 16 * wr + g, lr1 = lr0 + 8;
    const int gr0 = I + lr0, gr1 = I + lr1;
    const float nI0 = g_norm[wg][gr0], nI1 = g_norm[wg][gr1];

    float dv[4][4];
#pragma unroll
    for (int t = 0; t < 4; ++t) {
        const int colL = 32 * wc + 8 * t + 2 * tig;
        const int gcA = J + colL, gcB = gcA + 1;
        const float nJA = g_norm[wg][gcA], nJB = g_norm[wg][gcB];
        float d00 = sqrtf(fmaxf(nI0 + nJA - 2.f * cc[t][0], 0.f) + 1e-12f);
        float d01 = sqrtf(fmaxf(nI0 + nJB - 2.f * cc[t][1], 0.f) + 1e-12f);
        float d10 = sqrtf(fmaxf(nI1 + nJA - 2.f * cc[t][2], 0.f) + 1e-12f);
        float d11 = sqrtf(fmaxf(nI1 + nJB - 2.f * cc[t][3], 0.f) + 1e-12f);
        if (gr0 == gcA) d00 = 1e-6f;
        if (gr0 == gcB) d01 = 1e-6f;
        if (gr1 == gcA) d10 = 1e-6f;
        if (gr1 == gcB) d11 = 1e-6f;
        dv[t][0] = d00; dv[t][1] = d01; dv[t][2] = d10; dv[t][3] = d11;
    }

    if (wg == 1) {
        // stage y-distances + y statistics
        float pyy = 0.f, pr0 = 0.f, pr1 = 0.f;
#pragma unroll
        for (int t = 0; t < 4; ++t) {
            const int colL = 32 * wc + 8 * t + 2 * tig;
            gy[lr0 * 65 + colL]     = dv[t][0];
            gy[lr0 * 65 + colL + 1] = dv[t][1];
            gy[lr1 * 65 + colL]     = dv[t][2];
            gy[lr1 * 65 + colL + 1] = dv[t][3];
            pyy += dv[t][0]*dv[t][0] + dv[t][1]*dv[t][1] + dv[t][2]*dv[t][2] + dv[t][3]*dv[t][3];
            pr0 += dv[t][0] + dv[t][1];
            pr1 += dv[t][2] + dv[t][3];
            float vA = dv[t][0] + dv[t][2], vB = dv[t][1] + dv[t][3];
#pragma unroll
            for (int s = 16; s >= 4; s >>= 1) {
                vA += __shfl_down_sync(0xffffffffu, vA, s);
                vB += __shfl_down_sync(0xffffffffu, vB, s);
            }
            if (g == 0) {
                atomicAdd(&sh_cs[1][colL],     vA);
                atomicAdd(&sh_cs[1][colL + 1], vB);
            }
        }
        pr0 += __shfl_down_sync(0xffffffffu, pr0, 2, 4);
        pr0 += __shfl_down_sync(0xffffffffu, pr0, 1, 4);
        pr1 += __shfl_down_sync(0xffffffffu, pr1, 2, 4);
        pr1 += __shfl_down_sync(0xffffffffu, pr1, 1, 4);
        if (tig == 0) {
            atomicAdd(&sh_rs[1][lr0], pr0);
            atomicAdd(&sh_rs[1][lr1], pr1);
        }
#pragma unroll
        for (int off = 16; off > 0; off >>= 1)
            pyy += __shfl_down_sync(0xffffffffu, pyy, off);
        if (lane == 0) sh_p[2][warp8] = pyy;
    }
    __syncthreads();   // gy + y-stats ready

    if (wg == 0) {
        float pxy = 0.f, pxx = 0.f, pr0 = 0.f, pr1 = 0.f;
#pragma unroll
        for (int t = 0; t < 4; ++t) {
            const int colL = 32 * wc + 8 * t + 2 * tig;
            const float dy00 = gy[lr0 * 65 + colL];
            const float dy01 = gy[lr0 * 65 + colL + 1];
            const float dy10 = gy[lr1 * 65 + colL];
            const float dy11 = gy[lr1 * 65 + colL + 1];
            pxy += dv[t][0]*dy00 + dv[t][1]*dy01 + dv[t][2]*dy10 + dv[t][3]*dy11;
            pxx += dv[t][0]*dv[t][0] + dv[t][1]*dv[t][1] + dv[t][2]*dv[t][2] + dv[t][3]*dv[t][3];
            pr0 += dv[t][0] + dv[t][1];
            pr1 += dv[t][2] + dv[t][3];
            float vA = dv[t][0] + dv[t][2], vB = dv[t][1] + dv[t][3];
#pragma unroll
            for (int s = 16; s >= 4; s >>= 1) {
                vA += __shfl_down_sync(0xffffffffu, vA, s);
                vB += __shfl_down_sync(0xffffffffu, vB, s);
            }
            if (g == 0) {
                atomicAdd(&sh_cs[0][colL],     vA);
                atomicAdd(&sh_cs[0][colL + 1], vB);
            }
        }
        pr0 += __shfl_down_sync(0xffffffffu, pr0, 2, 4);
        pr0 += __shfl_down_sync(0xffffffffu, pr0, 1, 4);
        pr1 += __shfl_down_sync(0xffffffffu, pr1, 2, 4);
        pr1 += __shfl_down_sync(0xffffffffu, pr1, 1, 4);
        if (tig == 0) {
            atomicAdd(&sh_rs[0][lr0], pr0);
            atomicAdd(&sh_rs[0][lr1], pr1);
        }
#pragma unroll
        for (int off = 16; off > 0; off >>= 1) {
            pxy += __shfl_down_sync(0xffffffffu, pxy, off);
            pxx += __shfl_down_sync(0xffffffffu, pxx, off);
        }
        if (lane == 0) { sh_p[0][warp8] = pxy; sh_p[1][warp8] = pxx; }
    }
    __syncthreads();

    if (tid < 64) {
        atomicAdd(&g_rs[0][I + tid], sh_rs[0][tid]);
        atomicAdd(&g_rs[1][I + tid], sh_rs[1][tid]);
        if (!diag) {
            atomicAdd(&g_rs[0][J + tid], sh_cs[0][tid]);
            atomicAdd(&g_rs[1][J + tid], sh_cs[1][tid]);
        }
    }
    if (tid == 0) {
        const double scl = diag ? 1.0 : 2.0;
        double s0 = 0, s1 = 0, s2 = 0;
#pragma unroll
        for (int q = 0; q < 8; ++q) { s0 += sh_p[0][q]; s1 += sh_p[1][q]; s2 += sh_p[2][q]; }
        atomicAdd(&g_acc[0], scl * s0);
        atomicAdd(&g_acc[1], scl * s1);
        atomicAdd(&g_acc[2], scl * s2);
    }

    // -------- last-block finalize (threadfence + ticket) --------
    __threadfence();
    __syncthreads();
    if (tid == 0) s_last = (atomicAdd(&g_ticket, 1u) == NBLK - 1) ? 1u : 0u;
    __syncthreads();
    if (s_last == 0u) return;
    __threadfence();

    double sRR = 0.0, sXX = 0.0, sYY = 0.0, sX = 0.0, sY = 0.0;
#pragma unroll
    for (int q = 0; q < 2; ++q) {
        const int i = tid + q * 512;
        const double rx = (double)g_rs[0][i];
        const double ry = (double)g_rs[1][i];
        sRR += rx * ry; sXX += rx * rx; sYY += ry * ry; sX += rx; sY += ry;
    }
#pragma unroll
    for (int off = 16; off > 0; off >>= 1) {
        sRR += __shfl_down_sync(0xffffffffu, sRR, off);
        sXX += __shfl_down_sync(0xffffffffu, sXX, off);
        sYY += __shfl_down_sync(0xffffffffu, sYY, off);
        sX  += __shfl_down_sync(0xffffffffu, sX, off);
        sY  += __shfl_down_sync(0xffffffffu, sY, off);
    }
    __shared__ double sd[5][16];
    const int wfull = tid >> 5;
    if (lane == 0) { sd[0][wfull] = sRR; sd[1][wfull] = sXX; sd[2][wfull] = sYY; sd[3][wfull] = sX; sd[4][wfull] = sY; }
    __syncthreads();
    if (tid == 0) {
        double a0 = 0, a1 = 0, a2 = 0, a3 = 0, a4 = 0;
#pragma unroll
        for (int q = 0; q < 16; ++q) {
            a0 += sd[0][q]; a1 += sd[1][q]; a2 += sd[2][q]; a3 += sd[3][q]; a4 += sd[4][q];
        }
        const double N = (double)NPTS, N2 = N * N;
        const double sumab = g_acc[0] - (2.0 / N) * a0 + (a3 * a4) / N2;
        const double sumaa = g_acc[1] - (2.0 / N) * a1 + (a3 * a3) / N2;
        const double sumbb = g_acc[2] - (2.0 / N) * a2 + (a4 * a4) / N2;
        const double mxy = sumab / N2, mxx = sumaa / N2, myy = sumbb / N2;
        const double r = mxy / sqrt(mxx * myy + 1e-9);
        out[0] = (float)(1.0 - r);
    }
}

extern "C" void kernel_launch(void* const* d_in, const int* in_sizes, int n_in,
                              void* d_out, int out_size) {
    const float* a = (const float*)d_in[0];  // output_1 (1024,64,256) f32
    const float* b = (const float*)d_in[1];  // feature  (1024,64,256) f32
    // d_in[2] = mask, unused by the reference module.

    mean_norm_kernel<<<dim3(NPTS / 2, 2), 256>>>(a, b);
    gemm_mma_kernel<<<NBLK, 512>>>((float*)d_out);
}

// round 11
// speedup vs baseline: 1.8071x; 1.1019x over previous
#include <cuda_runtime.h>
#include <math.h>

#define NPTS 1024
#define TLEN 64
#define CDIM 256
#define NTILE 16                         // 1024 / 64
#define NBLK (NTILE * (NTILE + 1) / 2)   // 136 triangular tiles

typedef unsigned int uint32;

// Scratch (__device__ globals — no allocation allowed).
__device__ uint32 g_xtf[2][NPTS * CDIM]; // time-means pre-converted to tf32 bits
__device__ float  g_norm[2][NPTS];       // row squared norms (fp32 exact)
__device__ float  g_rs[2][NPTS];         // row sums of d (atomic-accumulated)
__device__ double g_acc[3];              // sum(dx*dy), sum(dx*dx), sum(dy*dy)
__device__ unsigned int g_ticket;        // last-block-done counter

__device__ __forceinline__ uint32 f2tf(float v) {
    uint32 r;
    asm("cvt.rna.tf32.f32 %0, %1;" : "=r"(r) : "f"(v));
    return r;
}
__device__ __forceinline__ void mma_tf32(float* c,
                                         uint32 a0, uint32 a1, uint32 a2, uint32 a3,
                                         uint32 b0, uint32 b1) {
    asm("mma.sync.aligned.m16n8k8.row.col.f32.tf32.tf32.f32 "
        "{%0,%1,%2,%3},{%4,%5,%6,%7},{%8,%9},{%0,%1,%2,%3};"
        : "+f"(c[0]), "+f"(c[1]), "+f"(c[2]), "+f"(c[3])
        : "r"(a0), "r"(a1), "r"(a2), "r"(a3), "r"(b0), "r"(b1));
}

// ---------------------------------------------------------------------------
// Kernel 1: time-mean over T + per-row squared norm + tf32 pre-conversion.
// (proven: HBM-ceiling bound, ~24.5us) grid (512, 2), block 256.
// ---------------------------------------------------------------------------
__global__ void mean_norm_kernel(const float* __restrict__ a,
                                 const float* __restrict__ b) {
    const int w = blockIdx.y;
    const float* __restrict__ src = (w == 0) ? a : b;
    const int tid  = threadIdx.x;
    const int row  = tid >> 7;
    const int half = (tid >> 6) & 1;
    const int c4   = tid & 63;
    const int n    = blockIdx.x * 2 + row;

    if (blockIdx.x == 0) {   // fold init
#pragma unroll
        for (int r = 0; r < 4; ++r) g_rs[w][tid + 256 * r] = 0.f;
        if (w == 0 && tid == 0) {
            g_acc[0] = 0.0; g_acc[1] = 0.0; g_acc[2] = 0.0;
            g_ticket = 0u;
        }
    }

    const float4* __restrict__ p =
        (const float4*)(src + (size_t)n * (TLEN * CDIM)) + half * 32 * (CDIM / 4) + c4;
    float4 s0 = make_float4(0.f, 0.f, 0.f, 0.f);
    float4 s1 = make_float4(0.f, 0.f, 0.f, 0.f);
#pragma unroll
    for (int t = 0; t < 16; ++t) {
        float4 v0 = __ldcs(p + (size_t)(2 * t) * (CDIM / 4));
        float4 v1 = __ldcs(p + (size_t)(2 * t + 1) * (CDIM / 4));
        s0.x += v0.x; s0.y += v0.y; s0.z += v0.z; s0.w += v0.w;
        s1.x += v1.x; s1.y += v1.y; s1.z += v1.z; s1.w += v1.w;
    }
    float4 s;
    s.x = s0.x + s1.x; s.y = s0.y + s1.y; s.z = s0.z + s1.z; s.w = s0.w + s1.w;

    __shared__ float4 sh[2][2][64];
    __shared__ float part[2][2];
    sh[row][half][c4] = s;
    __syncthreads();

    if (half == 0) {
        const float4 o = sh[row][1][c4];
        const float inv = 1.0f / TLEN;
        float4 m;
        m.x = (s.x + o.x) * inv; m.y = (s.y + o.y) * inv;
        m.z = (s.z + o.z) * inv; m.w = (s.w + o.w) * inv;

        uint4 u;
        u.x = f2tf(m.x); u.y = f2tf(m.y); u.z = f2tf(m.z); u.w = f2tf(m.w);
        ((uint4*)(g_xtf[w] + (size_t)n * CDIM))[c4] = u;

        float sq = m.x * m.x + m.y * m.y + m.z * m.z + m.w * m.w;
#pragma unroll
        for (int off = 16; off > 0; off >>= 1)
            sq += __shfl_down_sync(0xffffffffu, sq, off);
        if ((c4 & 31) == 0) part[row][c4 >> 5] = sq;
    }
    __syncthreads();
    if ((tid & 127) == 0) g_norm[w][n] = part[row][0] + part[row][1];
}

// ---------------------------------------------------------------------------
// Kernel 2: triangular tf32-mma pairwise-distance GEMM, 256 threads, 8 warps:
//   warps 0-3: x-matrix, 2x2 grid of 32x32 warp tiles
//   warps 4-7: y-matrix, same positions (1:1 exchange for pxy)
// LDS:MMA ratio 2.0 (was 3.0). Fused stats + ticket finalize. grid 136.
// ---------------------------------------------------------------------------
__global__ void __launch_bounds__(256) gemm_mma_kernel(float* __restrict__ out) {
    const int tb = blockIdx.x;
    int by = (int)((__fsqrt_rn(8.f * (float)tb + 1.f) - 1.f) * 0.5f);
    while ((by + 1) * (by + 2) / 2 <= tb) ++by;
    while (by * (by + 1) / 2 > tb) --by;
    const int bx = tb - by * (by + 1) / 2;
    const bool diag = (bx == by);
    const int I = bx * 64;   // rows
    const int J = by * 64;   // cols

    __shared__ uint32 sA[2][64][36];   // [mat][m][k] tf32 bits (I-rows), 18.4KB
    __shared__ uint32 sB[2][64][36];   // [mat][n][k] tf32 bits (J-rows), 18.4KB
    __shared__ float sh_rs[2][64], sh_cs[2][64];
    __shared__ float sh_p[3][4];
    __shared__ unsigned int s_last;

    float* gyv = (float*)&sA[0][0][0]; // overlay after mainloop: 4096 floats

    const int tid  = threadIdx.x;          // 0..255
    const int warp = tid >> 5, lane = tid & 31;
    const int mat  = warp >> 2;            // 0: x, 1: y
    const int w4   = warp & 3;
    const int wr = w4 >> 1, wc = w4 & 1;   // 2x2 grid of 32x32 warp tiles
    const int g = lane >> 2, tig = lane & 3;

    if (tid < 128) {
        const int w2 = tid >> 6;
        sh_rs[w2][tid & 63] = 0.f;
        sh_cs[w2][tid & 63] = 0.f;
    }

    float cc[2][4][4];                     // [mi][t][q]
#pragma unroll
    for (int mi = 0; mi < 2; ++mi)
#pragma unroll
        for (int t = 0; t < 4; ++t)
#pragma unroll
            for (int q = 0; q < 4; ++q) cc[mi][t][q] = 0.f;

    // fill mapping: m = tid>>2 (0..63), kq = (tid&3)*8 : 8 uint32 (2 uint4)
    const int m  = tid >> 2;
    const int kq = (tid & 3) * 8;

    uint4 fA[2][2], fB[2][2];
#pragma unroll
    for (int w = 0; w < 2; ++w)
#pragma unroll
        for (int q = 0; q < 2; ++q) {
            fA[w][q] = *(const uint4*)(g_xtf[w] + (size_t)(I + m) * CDIM + kq + 4 * q);
            fB[w][q] = *(const uint4*)(g_xtf[w] + (size_t)(J + m) * CDIM + kq + 4 * q);
        }

    const int rb0 = 32 * wr + g;           // mi=0 row base
    const int nb  = 32 * wc + g;           // col base (plus 8*t)

    for (int c = 0; c < 8; ++c) {
        __syncthreads();
#pragma unroll
        for (int w = 0; w < 2; ++w)
#pragma unroll
            for (int q = 0; q < 2; ++q) {
                *(uint4*)&sA[w][m][kq + 4 * q] = fA[w][q];
                *(uint4*)&sB[w][m][kq + 4 * q] = fB[w][q];
            }
        __syncthreads();
        if (c < 7) {
            const int k0 = (c + 1) * 32;
#pragma unroll
            for (int w = 0; w < 2; ++w)
#pragma unroll
                for (int q = 0; q < 2; ++q) {
                    fA[w][q] = *(const uint4*)(g_xtf[w] + (size_t)(I + m) * CDIM + k0 + kq + 4 * q);
                    fB[w][q] = *(const uint4*)(g_xtf[w] + (size_t)(J + m) * CDIM + k0 + kq + 4 * q);
                }
        }
#pragma unroll
        for (int kk = 0; kk < 4; ++kk) {
            const int kb = kk * 8;
            uint32 av[2][4];
#pragma unroll
            for (int mi = 0; mi < 2; ++mi) {
                const int r0 = rb0 + 16 * mi, r1 = r0 + 8;
                av[mi][0] = sA[mat][r0][kb + tig];
                av[mi][1] = sA[mat][r1][kb + tig];
                av[mi][2] = sA[mat][r0][kb + tig + 4];
                av[mi][3] = sA[mat][r1][kb + tig + 4];
            }
#pragma unroll
            for (int t = 0; t < 4; ++t) {
                const int nr = nb + 8 * t;
                const uint32 b0 = sB[mat][nr][kb + tig];
                const uint32 b1 = sB[mat][nr][kb + tig + 4];
                mma_tf32(cc[0][t], av[0][0], av[0][1], av[0][2], av[0][3], b0, b1);
                mma_tf32(cc[1][t], av[1][0], av[1][1], av[1][2], av[1][3], b0, b1);
            }
        }
    }

    __syncthreads();   // everyone done reading sA -> gyv overlay is safe

    // -------- distances for own matrix (diag override) --------
    float dv[2][4][4];
    float pss = 0.f;                        // pxx (x-warps) / pyy (y-warps)
#pragma unroll
    for (int mi = 0; mi < 2; ++mi) {
        const int gr0 = I + rb0 + 16 * mi, gr1 = gr0 + 8;
        const float nI0 = g_norm[mat][gr0], nI1 = g_norm[mat][gr1];
#pragma unroll
        for (int t = 0; t < 4; ++t) {
            const int colL = 32 * wc + 8 * t + 2 * tig;
            const int gcA = J + colL, gcB = gcA + 1;
            const float nJA = g_norm[mat][gcA], nJB = g_norm[mat][gcB];
            float d00 = sqrtf(fmaxf(nI0 + nJA - 2.f * cc[mi][t][0], 0.f) + 1e-12f);
            float d01 = sqrtf(fmaxf(nI0 + nJB - 2.f * cc[mi][t][1], 0.f) + 1e-12f);
            float d10 = sqrtf(fmaxf(nI1 + nJA - 2.f * cc[mi][t][2], 0.f) + 1e-12f);
            float d11 = sqrtf(fmaxf(nI1 + nJB - 2.f * cc[mi][t][3], 0.f) + 1e-12f);
            if (gr0 == gcA) d00 = 1e-6f;
            if (gr0 == gcB) d01 = 1e-6f;
            if (gr1 == gcA) d10 = 1e-6f;
            if (gr1 == gcB) d11 = 1e-6f;
            dv[mi][t][0] = d00; dv[mi][t][1] = d01;
            dv[mi][t][2] = d10; dv[mi][t][3] = d11;
            pss += d00 * d00 + d01 * d01 + d10 * d10 + d11 * d11;
        }
    }

    // own-matrix row sums / col sums (smem atomics; 2 warps share rows/cols)
#pragma unroll
    for (int mi = 0; mi < 2; ++mi) {
        float pr0 = 0.f, pr1 = 0.f;
#pragma unroll
        for (int t = 0; t < 4; ++t) {
            pr0 += dv[mi][t][0] + dv[mi][t][1];
            pr1 += dv[mi][t][2] + dv[mi][t][3];
        }
        pr0 += __shfl_down_sync(0xffffffffu, pr0, 2, 4);
        pr0 += __shfl_down_sync(0xffffffffu, pr0, 1, 4);
        pr1 += __shfl_down_sync(0xffffffffu, pr1, 2, 4);
        pr1 += __shfl_down_sync(0xffffffffu, pr1, 1, 4);
        if (tig == 0) {
            atomicAdd(&sh_rs[mat][rb0 + 16 * mi],     pr0);
            atomicAdd(&sh_rs[mat][rb0 + 16 * mi + 8], pr1);
        }
    }
#pragma unroll
    for (int t = 0; t < 4; ++t) {
        const int colL = 32 * wc + 8 * t + 2 * tig;
        float vA = dv[0][t][0] + dv[0][t][2] + dv[1][t][0] + dv[1][t][2];
        float vB = dv[0][t][1] + dv[0][t][3] + dv[1][t][1] + dv[1][t][3];
#pragma unroll
        for (int s = 16; s >= 4; s >>= 1) {
            vA += __shfl_down_sync(0xffffffffu, vA, s);
            vB += __shfl_down_sync(0xffffffffu, vB, s);
        }
        if (g == 0) {
            atomicAdd(&sh_cs[mat][colL],     vA);
            atomicAdd(&sh_cs[mat][colL + 1], vB);
        }
    }

    // y-warps stage distances for the x-warps' cross product
    if (mat == 1) {
#pragma unroll
        for (int mi = 0; mi < 2; ++mi)
#pragma unroll
            for (int t = 0; t < 4; ++t)
                *(float4*)&gyv[((((w4 * 2 + mi) * 4 + t) * 32) + lane) * 4] =
                    make_float4(dv[mi][t][0], dv[mi][t][1], dv[mi][t][2], dv[mi][t][3]);
        float pyy = pss;
#pragma unroll
        for (int off = 16; off > 0; off >>= 1)
            pyy += __shfl_down_sync(0xffffffffu, pyy, off);
        if (lane == 0) sh_p[2][w4] = pyy;
    }
    __syncthreads();   // gyv + y-stats visible

    if (mat == 0) {
        float pxy = 0.f;
#pragma unroll
        for (int mi = 0; mi < 2; ++mi)
#pragma unroll
            for (int t = 0; t < 4; ++t) {
                const float4 dy = *(const float4*)&gyv[((((w4 * 2 + mi) * 4 + t) * 32) + lane) * 4];
                pxy += dv[mi][t][0] * dy.x + dv[mi][t][1] * dy.y +
                       dv[mi][t][2] * dy.z + dv[mi][t][3] * dy.w;
            }
        float pxx = pss;
#pragma unroll
        for (int off = 16; off > 0; off >>= 1) {
            pxy += __shfl_down_sync(0xffffffffu, pxy, off);
            pxx += __shfl_down_sync(0xffffffffu, pxx, off);
        }
        if (lane == 0) { sh_p[0][w4] = pxy; sh_p[1][w4] = pxx; }
    }
    __syncthreads();

    if (tid < 64) {
        atomicAdd(&g_rs[0][I + tid], sh_rs[0][tid]);
        atomicAdd(&g_rs[1][I + tid], sh_rs[1][tid]);
        if (!diag) {
            atomicAdd(&g_rs[0][J + tid], sh_cs[0][tid]);
            atomicAdd(&g_rs[1][J + tid], sh_cs[1][tid]);
        }
    }
    if (tid == 0) {
        const double scl = diag ? 1.0 : 2.0;
        double s0 = 0, s1 = 0, s2 = 0;
#pragma unroll
        for (int q = 0; q < 4; ++q) { s0 += sh_p[0][q]; s1 += sh_p[1][q]; s2 += sh_p[2][q]; }
        atomicAdd(&g_acc[0], scl * s0);
        atomicAdd(&g_acc[1], scl * s1);
        atomicAdd(&g_acc[2], scl * s2);
    }

    // -------- last-block finalize (threadfence + ticket) --------
    __threadfence();
    __syncthreads();
    if (tid == 0) s_last = (atomicAdd(&g_ticket, 1u) == NBLK - 1) ? 1u : 0u;
    __syncthreads();
    if (s_last == 0u) return;
    __threadfence();

    double sRR = 0.0, sXX = 0.0, sYY = 0.0, sX = 0.0, sY = 0.0;
#pragma unroll
    for (int q = 0; q < 4; ++q) {
        const int i = tid + q * 256;
        const double rx = (double)g_rs[0][i];
        const double ry = (double)g_rs[1][i];
        sRR += rx * ry; sXX += rx * rx; sYY += ry * ry; sX += rx; sY += ry;
    }
#pragma unroll
    for (int off = 16; off > 0; off >>= 1) {
        sRR += __shfl_down_sync(0xffffffffu, sRR, off);
        sXX += __shfl_down_sync(0xffffffffu, sXX, off);
        sYY += __shfl_down_sync(0xffffffffu, sYY, off);
        sX  += __shfl_down_sync(0xffffffffu, sX, off);
        sY  += __shfl_down_sync(0xffffffffu, sY, off);
    }
    __shared__ double sd[5][8];
    if (lane == 0) { sd[0][warp] = sRR; sd[1][warp] = sXX; sd[2][warp] = sYY; sd[3][warp] = sX; sd[4][warp] = sY; }
    __syncthreads();
    if (tid == 0) {
        double a0 = 0, a1 = 0, a2 = 0, a3 = 0, a4 = 0;
#pragma unroll
        for (int q = 0; q < 8; ++q) {
            a0 += sd[0][q]; a1 += sd[1][q]; a2 += sd[2][q]; a3 += sd[3][q]; a4 += sd[4][q];
        }
        const double N = (double)NPTS, N2 = N * N;
        const double sumab = g_acc[0] - (2.0 / N) * a0 + (a3 * a4) / N2;
        const double sumaa = g_acc[1] - (2.0 / N) * a1 + (a3 * a3) / N2;
        const double sumbb = g_acc[2] - (2.0 / N) * a2 + (a4 * a4) / N2;
        const double mxy = sumab / N2, mxx = sumaa / N2, myy = sumbb / N2;
        const double r = mxy / sqrt(mxx * myy + 1e-9);
        out[0] = (float)(1.0 - r);
    }
}

extern "C" void kernel_launch(void* const* d_in, const int* in_sizes, int n_in,
                              void* d_out, int out_size) {
    const float* a = (const float*)d_in[0];  // output_1 (1024,64,256) f32
    const float* b = (const float*)d_in[1];  // feature  (1024,64,256) f32
    // d_in[2] = mask, unused by the reference module.

    mean_norm_kernel<<<dim3(NPTS / 2, 2), 256>>>(a, b);
    gemm_mma_kernel<<<NBLK, 256>>>((float*)d_out);
}